// round 7
// baseline (speedup 1.0000x reference)
#include <cuda_runtime.h>
#include <cstdint>

#define BATCH 64
#define SEQ   1024
#define DIN   256
#define UNITS 512
#define NROUND (SEQ / 2)    // 512 two-step rounds

// ============================ Scan configuration ============================
#define TB 8
#define TU 32
#define NBC (BATCH / TB)    // 8 batch groups
#define NUC (UNITS / TU)    // 16 CTAs per group
#define SCAN_THREADS 512
#define NW 16               // warps per CTA
#define KCH (UNITS / NW)    // 32 k per warp
#define HS_STRIDE 12
#define RED_STRIDE 9

// Ping-pong tagged hidden state: word = (tag << 32) | float_bits(h)
__device__ unsigned long long g_Hx[2][BATCH * UNITS];
// Combined transition matrices and precomputed 2-step input term
__device__ float g_A [UNITS * UNITS];                 // A  = diag(1-it) + U*diag(it)
__device__ float g_A2[UNITS * UNITS];                 // A^2
__device__ float g_Gam[BATCH * NROUND * UNITS];       // Gam[b][r][u] = g_{2r} A + g_{2r+1}

// packed fp32x2 FMA (2x fp32 rate on sm_103a; ptxas never auto-emits this)
#define FMA2(acc, h, u) asm("fma.rn.f32x2 %0, %1, %2, %0;" : "+l"(acc) : "l"(h), "l"(u))

__device__ __forceinline__ unsigned long long dup_f32(float v) {
    unsigned long long r;
    asm("mov.b64 %0, {%1, %1};" : "=l"(r) : "f"(v));
    return r;
}
__device__ __forceinline__ void unpack2(unsigned long long v, float& lo, float& hi) {
    asm("mov.b64 {%0, %1}, %2;" : "=f"(lo), "=f"(hi) : "l"(v));
}
// Morally-strong relaxed GPU-scope 64-bit ops: single-copy atomic, L2 point.
__device__ __forceinline__ unsigned long long ld_poll(const unsigned long long* p) {
    unsigned long long v;
    asm volatile("ld.relaxed.gpu.global.b64 %0, [%1];" : "=l"(v) : "l"(p));
    return v;
}
__device__ __forceinline__ void st_tagged(unsigned long long* p, float h, unsigned tag) {
    unsigned long long v = ((unsigned long long)tag << 32) | (unsigned long long)__float_as_uint(h);
    asm volatile("st.relaxed.gpu.global.b64 [%0], %1;" :: "l"(p), "l"(v));
}

// ====================== clear tag buffers (cross-replay) ====================
__global__ void ltc_clear()
{
    unsigned long long* p = &g_Hx[0][0];
    int i = blockIdx.x * blockDim.x + threadIdx.x;
    const int total = 2 * BATCH * UNITS;
    for (; i < total; i += gridDim.x * blockDim.x)
        p[i] = 0ull;
}

// ====================== build A = diag(1-it) + U*diag(it) ===================
__global__ void build_A(const float* __restrict__ U, const float* __restrict__ tau)
{
    int u = threadIdx.x;
    int k = blockIdx.x;
    float it = 1.0f / tau[u];
    float v = U[k * UNITS + u] * it;
    if (k == u) v += 1.0f - it;
    g_A[k * UNITS + u] = v;
}

// =============================== A2 = A @ A =================================
#define GBM 64
#define GBN 64
#define GBK 16

__global__ void __launch_bounds__(256)
gemm_A2()
{
    __shared__ float As[GBK][GBM + 4];
    __shared__ float Bs[GBK][GBN];

    const int tid = threadIdx.x;
    const int bx = blockIdx.x, by = blockIdx.y;
    const int arow = tid >> 2, akq = tid & 3;
    const int bkr  = tid >> 4, bnq = tid & 15;
    const int ty   = tid >> 4, tx  = tid & 15;

    unsigned long long acc[4][2];
    #pragma unroll
    for (int i = 0; i < 4; i++) { acc[i][0] = 0ull; acc[i][1] = 0ull; }

    const size_t arow_g = (size_t)(by * GBM + arow) * UNITS;

    for (int k0 = 0; k0 < UNITS; k0 += GBK) {
        float4 av = *reinterpret_cast<const float4*>(&g_A[arow_g + k0 + akq * 4]);
        As[akq * 4 + 0][arow] = av.x;
        As[akq * 4 + 1][arow] = av.y;
        As[akq * 4 + 2][arow] = av.z;
        As[akq * 4 + 3][arow] = av.w;
        float4 bv = *reinterpret_cast<const float4*>(&g_A[(size_t)(k0 + bkr) * UNITS + bx * GBN + bnq * 4]);
        *reinterpret_cast<float4*>(&Bs[bkr][bnq * 4]) = bv;
        __syncthreads();
        #pragma unroll
        for (int k = 0; k < GBK; k++) {
            float4 am = *reinterpret_cast<const float4*>(&As[k][ty * 4]);
            ulonglong2 bn = *reinterpret_cast<const ulonglong2*>(&Bs[k][tx * 4]);
            unsigned long long a0 = dup_f32(am.x), a1 = dup_f32(am.y);
            unsigned long long a2 = dup_f32(am.z), a3 = dup_f32(am.w);
            FMA2(acc[0][0], bn.x, a0); FMA2(acc[0][1], bn.y, a0);
            FMA2(acc[1][0], bn.x, a1); FMA2(acc[1][1], bn.y, a1);
            FMA2(acc[2][0], bn.x, a2); FMA2(acc[2][1], bn.y, a2);
            FMA2(acc[3][0], bn.x, a3); FMA2(acc[3][1], bn.y, a3);
        }
        __syncthreads();
    }
    const int n0 = bx * GBN + tx * 4;
    #pragma unroll
    for (int i = 0; i < 4; i++) {
        int m = by * GBM + ty * 4 + i;
        float c0, c1, c2, c3;
        unpack2(acc[i][0], c0, c1);
        unpack2(acc[i][1], c2, c3);
        *reinterpret_cast<float4*>(&g_A2[(size_t)m * UNITS + n0]) = make_float4(c0, c1, c2, c3);
    }
}

// ===================== Phase 1: G = inv_tau * (x@W + b) =====================
__global__ void __launch_bounds__(256)
ltc_gemm(const float* __restrict__ X,
         const float* __restrict__ Wm,
         const float* __restrict__ bias,
         const float* __restrict__ tau,
         float* __restrict__ G)
{
    __shared__ float As[GBK][GBM + 4];
    __shared__ float Bs[GBK][GBN];

    const int tid = threadIdx.x;
    const int bx = blockIdx.x, by = blockIdx.y;
    const int arow = tid >> 2, akq = tid & 3;
    const int bkr  = tid >> 4, bnq = tid & 15;
    const int ty   = tid >> 4, tx  = tid & 15;

    unsigned long long acc[4][2];
    #pragma unroll
    for (int i = 0; i < 4; i++) { acc[i][0] = 0ull; acc[i][1] = 0ull; }

    const size_t arow_g = (size_t)(by * GBM + arow) * DIN;

    for (int k0 = 0; k0 < DIN; k0 += GBK) {
        float4 av = *reinterpret_cast<const float4*>(&X[arow_g + k0 + akq * 4]);
        As[akq * 4 + 0][arow] = av.x;
        As[akq * 4 + 1][arow] = av.y;
        As[akq * 4 + 2][arow] = av.z;
        As[akq * 4 + 3][arow] = av.w;
        float4 bv = *reinterpret_cast<const float4*>(&Wm[(size_t)(k0 + bkr) * UNITS + bx * GBN + bnq * 4]);
        *reinterpret_cast<float4*>(&Bs[bkr][bnq * 4]) = bv;
        __syncthreads();
        #pragma unroll
        for (int k = 0; k < GBK; k++) {
            float4 am = *reinterpret_cast<const float4*>(&As[k][ty * 4]);
            ulonglong2 bn = *reinterpret_cast<const ulonglong2*>(&Bs[k][tx * 4]);
            unsigned long long a0 = dup_f32(am.x), a1 = dup_f32(am.y);
            unsigned long long a2 = dup_f32(am.z), a3 = dup_f32(am.w);
            FMA2(acc[0][0], bn.x, a0); FMA2(acc[0][1], bn.y, a0);
            FMA2(acc[1][0], bn.x, a1); FMA2(acc[1][1], bn.y, a1);
            FMA2(acc[2][0], bn.x, a2); FMA2(acc[2][1], bn.y, a2);
            FMA2(acc[3][0], bn.x, a3); FMA2(acc[3][1], bn.y, a3);
        }
        __syncthreads();
    }

    const int n0 = bx * GBN + tx * 4;
    float it0 = 1.0f / tau[n0 + 0], it1 = 1.0f / tau[n0 + 1];
    float it2 = 1.0f / tau[n0 + 2], it3 = 1.0f / tau[n0 + 3];
    float bb0 = bias[n0 + 0], bb1 = bias[n0 + 1], bb2 = bias[n0 + 2], bb3 = bias[n0 + 3];

    #pragma unroll
    for (int i = 0; i < 4; i++) {
        int m = by * GBM + ty * 4 + i;
        float c0, c1, c2, c3;
        unpack2(acc[i][0], c0, c1);
        unpack2(acc[i][1], c2, c3);
        float4 v;
        v.x = it0 * (c0 + bb0);
        v.y = it1 * (c1 + bb1);
        v.z = it2 * (c2 + bb2);
        v.w = it3 * (c3 + bb3);
        *reinterpret_cast<float4*>(&G[(size_t)m * UNITS + n0]) = v;
    }
}

// ============== Gamma prep: Gam[b][r] = G[b][2r]*A + G[b][2r+1] =============
__global__ void __launch_bounds__(256)
gemm_gam(const float* __restrict__ G)
{
    __shared__ float As[GBK][GBM + 4];
    __shared__ float Bs[GBK][GBN];

    const int tid = threadIdx.x;
    const int bx = blockIdx.x, by = blockIdx.y;
    const int arow = tid >> 2, akq = tid & 3;
    const int bkr  = tid >> 4, bnq = tid & 15;
    const int ty   = tid >> 4, tx  = tid & 15;

    const int bglob = by >> 3;
    const int r0    = (by & 7) * GBM;

    unsigned long long acc[4][2];
    #pragma unroll
    for (int i = 0; i < 4; i++) { acc[i][0] = 0ull; acc[i][1] = 0ull; }

    const size_t arow_g = ((size_t)bglob * SEQ + 2 * (r0 + arow)) * UNITS;

    for (int k0 = 0; k0 < UNITS; k0 += GBK) {
        float4 av = *reinterpret_cast<const float4*>(&G[arow_g + k0 + akq * 4]);
        As[akq * 4 + 0][arow] = av.x;
        As[akq * 4 + 1][arow] = av.y;
        As[akq * 4 + 2][arow] = av.z;
        As[akq * 4 + 3][arow] = av.w;
        float4 bv = *reinterpret_cast<const float4*>(&g_A[(size_t)(k0 + bkr) * UNITS + bx * GBN + bnq * 4]);
        *reinterpret_cast<float4*>(&Bs[bkr][bnq * 4]) = bv;
        __syncthreads();
        #pragma unroll
        for (int k = 0; k < GBK; k++) {
            float4 am = *reinterpret_cast<const float4*>(&As[k][ty * 4]);
            ulonglong2 bn = *reinterpret_cast<const ulonglong2*>(&Bs[k][tx * 4]);
            unsigned long long a0 = dup_f32(am.x), a1 = dup_f32(am.y);
            unsigned long long a2 = dup_f32(am.z), a3 = dup_f32(am.w);
            FMA2(acc[0][0], bn.x, a0); FMA2(acc[0][1], bn.y, a0);
            FMA2(acc[1][0], bn.x, a1); FMA2(acc[1][1], bn.y, a1);
            FMA2(acc[2][0], bn.x, a2); FMA2(acc[2][1], bn.y, a2);
            FMA2(acc[3][0], bn.x, a3); FMA2(acc[3][1], bn.y, a3);
        }
        __syncthreads();
    }

    const int n0 = bx * GBN + tx * 4;
    #pragma unroll
    for (int i = 0; i < 4; i++) {
        int r = r0 + ty * 4 + i;
        float c0, c1, c2, c3;
        unpack2(acc[i][0], c0, c1);
        unpack2(acc[i][1], c2, c3);
        float4 go = *reinterpret_cast<const float4*>(&G[((size_t)bglob * SEQ + 2 * r + 1) * UNITS + n0]);
        float4 v = make_float4(c0 + go.x, c1 + go.y, c2 + go.z, c3 + go.w);
        *reinterpret_cast<float4*>(&g_Gam[((size_t)bglob * NROUND + r) * UNITS + n0]) = v;
    }
}

// ============================ Phase 2: LTC scan =============================
// Per round r: h_next = h*A2 + Gam_r (CRITICAL, released first);
//              y = h*A + g_{2r}     (output-only, overlaps next poll).
__global__ void __launch_bounds__(SCAN_THREADS, 1)
ltc_scan(float* __restrict__ out)
{
    const int ju   = blockIdx.x;
    const int ib   = blockIdx.y;
    const int tid  = threadIdx.x;
    const int lane = tid & 31;
    const int w    = tid >> 5;
    const int u    = ju * TU + lane;
    const int kb   = w * KCH;
    const int bg0  = ib * TB;

    extern __shared__ float smem[];
    float* A2s  = smem;                              // [512][32] scalar A2 slice
    float* Hs   = A2s + UNITS * TU;                  // [512][HS_STRIDE]
    float* Red1 = Hs + UNITS * HS_STRIDE;            // [16][32][RED_STRIDE]
    float* Red2 = Red1 + NW * 32 * RED_STRIDE;

    // ---- A slice into registers (duplicated pairs) ----
    unsigned long long UU[KCH];
    #pragma unroll
    for (int i = 0; i < KCH; i++)
        UU[i] = dup_f32(g_A[(size_t)(kb + i) * UNITS + u]);

    // ---- A2 slice into smem ----
    for (int idx = tid; idx < UNITS * TU; idx += SCAN_THREADS) {
        int k = idx >> 5, ul = idx & 31;
        A2s[idx] = g_A2[(size_t)k * UNITS + ju * TU + ul];
    }

    // ---- h0 = 0, tag 1 ----
    if (tid < 256)
        st_tagged(&g_Hx[0][(bg0 + w) * UNITS + u], 0.0f, 1u);

    int cur = 0;
    for (int r = 0; r < NROUND; r++) {
        const unsigned want = (unsigned)(r + 1);

        // ---- Prefetch g_{2r} and Gam_r (overlap the poll) ----
        float gt = 0.0f, gam = 0.0f;
        size_t o = 0;
        if (tid < 256) {
            o   = ((size_t)(bg0 + w) * SEQ + 2 * r) * UNITS + u;
            gt  = out[o];
            gam = g_Gam[((size_t)(bg0 + w) * NROUND + r) * UNITS + u];
        }

        // ---- Poll exchange ----
        unsigned long long v[8];
        {
            const unsigned long long* src = &g_Hx[cur][tid];
            bool ok;
            do {
                ok = true;
                #pragma unroll
                for (int b = 0; b < 8; b++)
                    v[b] = ld_poll(&src[(size_t)(bg0 + b) * UNITS]);
                #pragma unroll
                for (int b = 0; b < 8; b++)
                    ok &= ((unsigned)(v[b] >> 32) == want);
            } while (!ok);
        }
        // ---- Stage into smem ----
        {
            float4* dst = reinterpret_cast<float4*>(&Hs[tid * HS_STRIDE]);
            dst[0] = make_float4(__uint_as_float((unsigned)v[0]), __uint_as_float((unsigned)v[1]),
                                 __uint_as_float((unsigned)v[2]), __uint_as_float((unsigned)v[3]));
            dst[1] = make_float4(__uint_as_float((unsigned)v[4]), __uint_as_float((unsigned)v[5]),
                                 __uint_as_float((unsigned)v[6]), __uint_as_float((unsigned)v[7]));
        }
        __syncthreads();   // S1

        // ---- CRITICAL dot first: h*A2 ----
        unsigned long long c0 = 0, c1 = 0, c2 = 0, c3 = 0;
        #pragma unroll
        for (int i = 0; i < KCH; i++) {
            const ulonglong2* hv = reinterpret_cast<const ulonglong2*>(&Hs[(kb + i) * HS_STRIDE]);
            ulonglong2 hA = hv[0];
            ulonglong2 hB = hv[1];
            unsigned long long u2 = dup_f32(A2s[(kb + i) * TU + lane]);
            FMA2(c0, hA.x, u2);
            FMA2(c1, hA.y, u2);
            FMA2(c2, hB.x, u2);
            FMA2(c3, hB.y, u2);
        }
        {
            float* r2 = &Red2[(w * 32 + lane) * RED_STRIDE];
            float x0, x1;
            unpack2(c0, x0, x1); r2[0] = x0; r2[1] = x1;
            unpack2(c1, x0, x1); r2[2] = x0; r2[3] = x1;
            unpack2(c2, x0, x1); r2[4] = x0; r2[5] = x1;
            unpack2(c3, x0, x1); r2[6] = x0; r2[7] = x1;
        }
        __syncthreads();   // S2

        // ---- Reduce s2 + RELEASE h_next to the group immediately ----
        float hn = 0.0f;
        if (tid < 256) {
            float s2 = 0.0f;
            #pragma unroll
            for (int ww = 0; ww < NW; ww++)
                s2 += Red2[(ww * 32 + lane) * RED_STRIDE + w];
            hn = s2 + gam;
            st_tagged(&g_Hx[cur ^ 1][(bg0 + w) * UNITS + u], hn, (unsigned)(r + 2));
        }

        // ---- Output dot: h*A (off the inter-CTA critical path) ----
        unsigned long long a0 = 0, a1 = 0, a2 = 0, a3 = 0;
        #pragma unroll
        for (int i = 0; i < KCH; i++) {
            const ulonglong2* hv = reinterpret_cast<const ulonglong2*>(&Hs[(kb + i) * HS_STRIDE]);
            ulonglong2 hA = hv[0];
            ulonglong2 hB = hv[1];
            FMA2(a0, hA.x, UU[i]);
            FMA2(a1, hA.y, UU[i]);
            FMA2(a2, hB.x, UU[i]);
            FMA2(a3, hB.y, UU[i]);
        }
        {
            float* r1 = &Red1[(w * 32 + lane) * RED_STRIDE];
            float x0, x1;
            unpack2(a0, x0, x1); r1[0] = x0; r1[1] = x1;
            unpack2(a1, x0, x1); r1[2] = x0; r1[3] = x1;
            unpack2(a2, x0, x1); r1[4] = x0; r1[5] = x1;
            unpack2(a3, x0, x1); r1[6] = x0; r1[7] = x1;
        }
        __syncthreads();   // S3

        if (tid < 256) {
            float s1 = 0.0f;
            #pragma unroll
            for (int ww = 0; ww < NW; ww++)
                s1 += Red1[(ww * 32 + lane) * RED_STRIDE + w];
            out[o] = s1 + gt;        // y_{2r}
            out[o + UNITS] = hn;     // y_{2r+1} = h_next
        }
        cur ^= 1;
        // Hs reuse is safe: next stage happens after this thread's S3 + poll;
        // all A-dot reads precede S3.
    }
}

// ================================ Launcher ==================================
extern "C" void kernel_launch(void* const* d_in, const int* in_sizes, int n_in,
                              void* d_out, int out_size)
{
    const float* x   = (const float*)d_in[0];   // [64,1024,256]
    const float* Wm  = (const float*)d_in[1];   // [256,512]
    const float* Um  = (const float*)d_in[2];   // [512,512]
    const float* bb  = (const float*)d_in[3];   // [512]
    const float* tau = (const float*)d_in[4];   // [512]
    float* out = (float*)d_out;                 // [64,1024,512]

    (void)in_sizes; (void)n_in; (void)out_size;

    ltc_clear<<<128, 256>>>();

    build_A<<<UNITS, UNITS>>>(Um, tau);
    gemm_A2<<<dim3(UNITS / GBN, UNITS / GBM), 256>>>();

    ltc_gemm<<<dim3(UNITS / GBN, (BATCH * SEQ) / GBM), 256>>>(x, Wm, bb, tau, out);

    gemm_gam<<<dim3(UNITS / GBN, (BATCH * NROUND) / GBM), 256>>>(out);

    const int smem_bytes = (UNITS * TU + UNITS * HS_STRIDE + 2 * NW * 32 * RED_STRIDE) * (int)sizeof(float);
    cudaFuncSetAttribute(ltc_scan, cudaFuncAttributeMaxDynamicSharedMemorySize, smem_bytes);
    ltc_scan<<<dim3(NUC, NBC), SCAN_THREADS, smem_bytes>>>(out);
}

// round 10
// speedup vs baseline: 1.1356x; 1.1356x over previous
#include <cuda_runtime.h>
#include <cstdint>

#define BATCH 64
#define SEQ   1024
#define DIN   256
#define UNITS 512
#define NR4   (SEQ / 4)     // 256 four-step rounds

// ============================ Scan configuration ============================
#define TB 8
#define TU 32
#define NBC (BATCH / TB)    // 8 batch groups
#define NUC (UNITS / TU)    // 16 CTAs per group
#define SCAN_THREADS 512
#define NW 16
#define KCH (UNITS / NW)    // 32 k per warp
#define HS_STRIDE 12
#define RED_STRIDE 9

// Ping-pong tagged hidden state: word = (tag << 32) | float_bits(h)
__device__ unsigned long long g_Hx[2][BATCH * UNITS];
// Transition matrix powers
__device__ float g_A [UNITS * UNITS];   // A  = diag(1-it) + U*diag(it)
__device__ float g_A2[UNITS * UNITS];
__device__ float g_A3[UNITS * UNITS];
__device__ float g_A4[UNITS * UNITS];
// Per-round input combinations (scratch, ~100MB total)
__device__ float g_Gm2[BATCH * NR4 * UNITS];   // g0 A + g1
__device__ float g_Gm3[BATCH * NR4 * UNITS];   // Gm2 A + g2
__device__ float g_Psi[BATCH * NR4 * UNITS];   // Gm3 A + g3

// packed fp32x2 FMA (2x fp32 rate on sm_103a; ptxas never auto-emits this)
#define FMA2(acc, h, u) asm("fma.rn.f32x2 %0, %1, %2, %0;" : "+l"(acc) : "l"(h), "l"(u))

__device__ __forceinline__ unsigned long long dup_f32(float v) {
    unsigned long long r;
    asm("mov.b64 %0, {%1, %1};" : "=l"(r) : "f"(v));
    return r;
}
__device__ __forceinline__ void unpack2(unsigned long long v, float& lo, float& hi) {
    asm("mov.b64 {%0, %1}, %2;" : "=f"(lo), "=f"(hi) : "l"(v));
}
__device__ __forceinline__ unsigned long long ld_poll(const unsigned long long* p) {
    unsigned long long v;
    asm volatile("ld.relaxed.gpu.global.b64 %0, [%1];" : "=l"(v) : "l"(p));
    return v;
}
__device__ __forceinline__ void st_tagged(unsigned long long* p, float h, unsigned tag) {
    unsigned long long v = ((unsigned long long)tag << 32) | (unsigned long long)__float_as_uint(h);
    asm volatile("st.relaxed.gpu.global.b64 [%0], %1;" :: "l"(p), "l"(v));
}

// ====================== clear tag buffers (cross-replay) ====================
__global__ void ltc_clear()
{
    unsigned long long* p = &g_Hx[0][0];
    int i = blockIdx.x * blockDim.x + threadIdx.x;
    const int total = 2 * BATCH * UNITS;
    for (; i < total; i += gridDim.x * blockDim.x)
        p[i] = 0ull;
}

// ====================== build A = diag(1-it) + U*diag(it) ===================
__global__ void build_A(const float* __restrict__ U, const float* __restrict__ tau)
{
    int u = threadIdx.x;
    int k = blockIdx.x;
    float it = 1.0f / tau[u];
    float v = U[k * UNITS + u] * it;
    if (k == u) v += 1.0f - it;
    g_A[k * UNITS + u] = v;
}

// ================== generic 512x512x512 GEMM: C = A @ B =====================
#define GBM 64
#define GBN 64
#define GBK 16

__global__ void __launch_bounds__(256)
gemm_sq(const float* __restrict__ Am, const float* __restrict__ Bm, float* __restrict__ Cm)
{
    __shared__ float As[GBK][GBM + 4];
    __shared__ float Bs[GBK][GBN];

    const int tid = threadIdx.x;
    const int bx = blockIdx.x, by = blockIdx.y;
    const int arow = tid >> 2, akq = tid & 3;
    const int bkr  = tid >> 4, bnq = tid & 15;
    const int ty   = tid >> 4, tx  = tid & 15;

    unsigned long long acc[4][2];
    #pragma unroll
    for (int i = 0; i < 4; i++) { acc[i][0] = 0ull; acc[i][1] = 0ull; }

    const size_t arow_g = (size_t)(by * GBM + arow) * UNITS;

    for (int k0 = 0; k0 < UNITS; k0 += GBK) {
        float4 av = *reinterpret_cast<const float4*>(&Am[arow_g + k0 + akq * 4]);
        As[akq * 4 + 0][arow] = av.x;
        As[akq * 4 + 1][arow] = av.y;
        As[akq * 4 + 2][arow] = av.z;
        As[akq * 4 + 3][arow] = av.w;
        float4 bv = *reinterpret_cast<const float4*>(&Bm[(size_t)(k0 + bkr) * UNITS + bx * GBN + bnq * 4]);
        *reinterpret_cast<float4*>(&Bs[bkr][bnq * 4]) = bv;
        __syncthreads();
        #pragma unroll
        for (int k = 0; k < GBK; k++) {
            float4 am = *reinterpret_cast<const float4*>(&As[k][ty * 4]);
            ulonglong2 bn = *reinterpret_cast<const ulonglong2*>(&Bs[k][tx * 4]);
            unsigned long long a0 = dup_f32(am.x), a1 = dup_f32(am.y);
            unsigned long long a2 = dup_f32(am.z), a3 = dup_f32(am.w);
            FMA2(acc[0][0], bn.x, a0); FMA2(acc[0][1], bn.y, a0);
            FMA2(acc[1][0], bn.x, a1); FMA2(acc[1][1], bn.y, a1);
            FMA2(acc[2][0], bn.x, a2); FMA2(acc[2][1], bn.y, a2);
            FMA2(acc[3][0], bn.x, a3); FMA2(acc[3][1], bn.y, a3);
        }
        __syncthreads();
    }
    const int n0 = bx * GBN + tx * 4;
    #pragma unroll
    for (int i = 0; i < 4; i++) {
        int m = by * GBM + ty * 4 + i;
        float c0, c1, c2, c3;
        unpack2(acc[i][0], c0, c1);
        unpack2(acc[i][1], c2, c3);
        *reinterpret_cast<float4*>(&Cm[(size_t)m * UNITS + n0]) = make_float4(c0, c1, c2, c3);
    }
}

// ===================== Phase 1: G = inv_tau * (x@W + b) =====================
__global__ void __launch_bounds__(256)
ltc_gemm(const float* __restrict__ X,
         const float* __restrict__ Wm,
         const float* __restrict__ bias,
         const float* __restrict__ tau,
         float* __restrict__ G)
{
    __shared__ float As[GBK][GBM + 4];
    __shared__ float Bs[GBK][GBN];

    const int tid = threadIdx.x;
    const int bx = blockIdx.x, by = blockIdx.y;
    const int arow = tid >> 2, akq = tid & 3;
    const int bkr  = tid >> 4, bnq = tid & 15;
    const int ty   = tid >> 4, tx  = tid & 15;

    unsigned long long acc[4][2];
    #pragma unroll
    for (int i = 0; i < 4; i++) { acc[i][0] = 0ull; acc[i][1] = 0ull; }

    const size_t arow_g = (size_t)(by * GBM + arow) * DIN;

    for (int k0 = 0; k0 < DIN; k0 += GBK) {
        float4 av = *reinterpret_cast<const float4*>(&X[arow_g + k0 + akq * 4]);
        As[akq * 4 + 0][arow] = av.x;
        As[akq * 4 + 1][arow] = av.y;
        As[akq * 4 + 2][arow] = av.z;
        As[akq * 4 + 3][arow] = av.w;
        float4 bv = *reinterpret_cast<const float4*>(&Wm[(size_t)(k0 + bkr) * UNITS + bx * GBN + bnq * 4]);
        *reinterpret_cast<float4*>(&Bs[bkr][bnq * 4]) = bv;
        __syncthreads();
        #pragma unroll
        for (int k = 0; k < GBK; k++) {
            float4 am = *reinterpret_cast<const float4*>(&As[k][ty * 4]);
            ulonglong2 bn = *reinterpret_cast<const ulonglong2*>(&Bs[k][tx * 4]);
            unsigned long long a0 = dup_f32(am.x), a1 = dup_f32(am.y);
            unsigned long long a2 = dup_f32(am.z), a3 = dup_f32(am.w);
            FMA2(acc[0][0], bn.x, a0); FMA2(acc[0][1], bn.y, a0);
            FMA2(acc[1][0], bn.x, a1); FMA2(acc[1][1], bn.y, a1);
            FMA2(acc[2][0], bn.x, a2); FMA2(acc[2][1], bn.y, a2);
            FMA2(acc[3][0], bn.x, a3); FMA2(acc[3][1], bn.y, a3);
        }
        __syncthreads();
    }

    const int n0 = bx * GBN + tx * 4;
    float it0 = 1.0f / tau[n0 + 0], it1 = 1.0f / tau[n0 + 1];
    float it2 = 1.0f / tau[n0 + 2], it3 = 1.0f / tau[n0 + 3];
    float bb0 = bias[n0 + 0], bb1 = bias[n0 + 1], bb2 = bias[n0 + 2], bb3 = bias[n0 + 3];

    #pragma unroll
    for (int i = 0; i < 4; i++) {
        int m = by * GBM + ty * 4 + i;
        float c0, c1, c2, c3;
        unpack2(acc[i][0], c0, c1);
        unpack2(acc[i][1], c2, c3);
        float4 v;
        v.x = it0 * (c0 + bb0);
        v.y = it1 * (c1 + bb1);
        v.z = it2 * (c2 + bb2);
        v.w = it3 * (c3 + bb3);
        *reinterpret_cast<float4*>(&G[(size_t)m * UNITS + n0]) = v;
    }
}

// ========== Gamma chain: dst[b,r] = Aop_row(b,r) @ A + G[b][4r+addc] ========
// Row (b, r): b = m>>8, r = m&255 for m in [0, 16384). Aop offset = b*sB + r*sR.
__global__ void __launch_bounds__(256)
gam_chain(const float* __restrict__ Aop, size_t sB, size_t sR,
          const float* __restrict__ G, int addc, float* __restrict__ dst)
{
    __shared__ float As[GBK][GBM + 4];
    __shared__ float Bs[GBK][GBN];

    const int tid = threadIdx.x;
    const int bx = blockIdx.x, by = blockIdx.y;
    const int arow = tid >> 2, akq = tid & 3;
    const int bkr  = tid >> 4, bnq = tid & 15;
    const int ty   = tid >> 4, tx  = tid & 15;

    const int bglob = by >> 2;            // 4 row-tiles per batch (256 r / 64)
    const int r0    = (by & 3) * GBM;

    unsigned long long acc[4][2];
    #pragma unroll
    for (int i = 0; i < 4; i++) { acc[i][0] = 0ull; acc[i][1] = 0ull; }

    const size_t arow_g = (size_t)bglob * sB + (size_t)(r0 + arow) * sR;

    for (int k0 = 0; k0 < UNITS; k0 += GBK) {
        float4 av = *reinterpret_cast<const float4*>(&Aop[arow_g + k0 + akq * 4]);
        As[akq * 4 + 0][arow] = av.x;
        As[akq * 4 + 1][arow] = av.y;
        As[akq * 4 + 2][arow] = av.z;
        As[akq * 4 + 3][arow] = av.w;
        float4 bv = *reinterpret_cast<const float4*>(&g_A[(size_t)(k0 + bkr) * UNITS + bx * GBN + bnq * 4]);
        *reinterpret_cast<float4*>(&Bs[bkr][bnq * 4]) = bv;
        __syncthreads();
        #pragma unroll
        for (int k = 0; k < GBK; k++) {
            float4 am = *reinterpret_cast<const float4*>(&As[k][ty * 4]);
            ulonglong2 bn = *reinterpret_cast<const ulonglong2*>(&Bs[k][tx * 4]);
            unsigned long long a0 = dup_f32(am.x), a1 = dup_f32(am.y);
            unsigned long long a2 = dup_f32(am.z), a3 = dup_f32(am.w);
            FMA2(acc[0][0], bn.x, a0); FMA2(acc[0][1], bn.y, a0);
            FMA2(acc[1][0], bn.x, a1); FMA2(acc[1][1], bn.y, a1);
            FMA2(acc[2][0], bn.x, a2); FMA2(acc[2][1], bn.y, a2);
            FMA2(acc[3][0], bn.x, a3); FMA2(acc[3][1], bn.y, a3);
        }
        __syncthreads();
    }

    const int n0 = bx * GBN + tx * 4;
    #pragma unroll
    for (int i = 0; i < 4; i++) {
        int r = r0 + ty * 4 + i;
        float c0, c1, c2, c3;
        unpack2(acc[i][0], c0, c1);
        unpack2(acc[i][1], c2, c3);
        float4 go = *reinterpret_cast<const float4*>(&G[((size_t)bglob * SEQ + 4 * r + addc) * UNITS + n0]);
        float4 v = make_float4(c0 + go.x, c1 + go.y, c2 + go.z, c3 + go.w);
        *reinterpret_cast<float4*>(&dst[((size_t)bglob * NR4 + r) * UNITS + n0]) = v;
    }
}

// ===== Post: out[4r+c] = h_{4r} @ A^{c+1} + {G[4r], Gm2, Gm3}, c = bx>>3 ====
// A-operand rows = out[4r-1] (scan output), zeros for r = 0.
__global__ void __launch_bounds__(256)
ltc_post(float* __restrict__ out)
{
    __shared__ float As[GBK][GBM + 4];
    __shared__ float Bs[GBK][GBN];

    const int tid = threadIdx.x;
    const int bx = blockIdx.x, by = blockIdx.y;   // bx 0..23, by 0..255
    const int arow = tid >> 2, akq = tid & 3;
    const int bkr  = tid >> 4, bnq = tid & 15;
    const int ty   = tid >> 4, tx  = tid & 15;

    const int bglob = by >> 2;
    const int r0    = (by & 3) * GBM;
    const int c     = bx >> 3;                    // power block: 0->A, 1->A2, 2->A3
    const int nb    = bx & 7;                     // n tile within 512

    const float* Bsrc = (c == 0) ? g_A : (c == 1) ? g_A2 : g_A3;

    unsigned long long acc[4][2];
    #pragma unroll
    for (int i = 0; i < 4; i++) { acc[i][0] = 0ull; acc[i][1] = 0ull; }

    const int rr = r0 + arow;
    // h_{4r} = out row (4r - 1); zeros for r == 0
    const size_t arow_g = ((size_t)bglob * SEQ + 4 * rr - 1) * UNITS;
    const bool avalid = (rr > 0);

    for (int k0 = 0; k0 < UNITS; k0 += GBK) {
        float4 av = make_float4(0.f, 0.f, 0.f, 0.f);
        if (avalid)
            av = *reinterpret_cast<const float4*>(&out[arow_g + k0 + akq * 4]);
        As[akq * 4 + 0][arow] = av.x;
        As[akq * 4 + 1][arow] = av.y;
        As[akq * 4 + 2][arow] = av.z;
        As[akq * 4 + 3][arow] = av.w;
        float4 bv = *reinterpret_cast<const float4*>(&Bsrc[(size_t)(k0 + bkr) * UNITS + nb * GBN + bnq * 4]);
        *reinterpret_cast<float4*>(&Bs[bkr][bnq * 4]) = bv;
        __syncthreads();
        #pragma unroll
        for (int k = 0; k < GBK; k++) {
            float4 am = *reinterpret_cast<const float4*>(&As[k][ty * 4]);
            ulonglong2 bn = *reinterpret_cast<const ulonglong2*>(&Bs[k][tx * 4]);
            unsigned long long a0 = dup_f32(am.x), a1 = dup_f32(am.y);
            unsigned long long a2 = dup_f32(am.z), a3 = dup_f32(am.w);
            FMA2(acc[0][0], bn.x, a0); FMA2(acc[0][1], bn.y, a0);
            FMA2(acc[1][0], bn.x, a1); FMA2(acc[1][1], bn.y, a1);
            FMA2(acc[2][0], bn.x, a2); FMA2(acc[2][1], bn.y, a2);
            FMA2(acc[3][0], bn.x, a3); FMA2(acc[3][1], bn.y, a3);
        }
        __syncthreads();
    }

    const int n0 = nb * GBN + tx * 4;
    #pragma unroll
    for (int i = 0; i < 4; i++) {
        int r = r0 + ty * 4 + i;
        float c0, c1, c2, c3;
        unpack2(acc[i][0], c0, c1);
        unpack2(acc[i][1], c2, c3);
        size_t doff = ((size_t)bglob * SEQ + 4 * r + c) * UNITS + n0;
        float4 ad;
        if (c == 0)      ad = *reinterpret_cast<const float4*>(&out[doff]);      // g_{4r} (still intact)
        else if (c == 1) ad = *reinterpret_cast<const float4*>(&g_Gm2[((size_t)bglob * NR4 + r) * UNITS + n0]);
        else             ad = *reinterpret_cast<const float4*>(&g_Gm3[((size_t)bglob * NR4 + r) * UNITS + n0]);
        *reinterpret_cast<float4*>(&out[doff]) =
            make_float4(c0 + ad.x, c1 + ad.y, c2 + ad.z, c3 + ad.w);
    }
}

// ============================ Phase 2: LTC scan =============================
// Per round r (4 timesteps): h_{4r+4} = h_{4r} @ A4 + Psi_r -> out[4r+3].
__global__ void __launch_bounds__(SCAN_THREADS, 1)
ltc_scan(float* __restrict__ out)
{
    const int ju   = blockIdx.x;
    const int ib   = blockIdx.y;
    const int tid  = threadIdx.x;
    const int lane = tid & 31;
    const int w    = tid >> 5;
    const int u    = ju * TU + lane;
    const int kb   = w * KCH;
    const int bg0  = ib * TB;

    __shared__ float Hs[UNITS * HS_STRIDE];
    __shared__ float Red[NW * 32 * RED_STRIDE];

    // ---- A4 slice into registers (duplicated pairs) ----
    unsigned long long UU[KCH];
    #pragma unroll
    for (int i = 0; i < KCH; i++)
        UU[i] = dup_f32(g_A4[(size_t)(kb + i) * UNITS + u]);

    // ---- h0 = 0, tag 1 ----
    if (tid < 256)
        st_tagged(&g_Hx[0][(bg0 + w) * UNITS + u], 0.0f, 1u);

    int cur = 0;
    for (int r = 0; r < NR4; r++) {
        const unsigned want = (unsigned)(r + 1);

        // ---- Prefetch Psi_r (overlaps the poll) ----
        float psi = 0.0f;
        size_t o3 = 0;
        if (tid < 256) {
            o3  = ((size_t)(bg0 + w) * SEQ + 4 * r + 3) * UNITS + u;
            psi = g_Psi[((size_t)(bg0 + w) * NR4 + r) * UNITS + u];
        }

        // ---- Poll exchange ----
        unsigned long long v[8];
        {
            const unsigned long long* src = &g_Hx[cur][tid];
            bool ok;
            do {
                ok = true;
                #pragma unroll
                for (int b = 0; b < 8; b++)
                    v[b] = ld_poll(&src[(size_t)(bg0 + b) * UNITS]);
                #pragma unroll
                for (int b = 0; b < 8; b++)
                    ok &= ((unsigned)(v[b] >> 32) == want);
            } while (!ok);
        }
        // ---- Stage into smem ----
        {
            float4* dst = reinterpret_cast<float4*>(&Hs[tid * HS_STRIDE]);
            dst[0] = make_float4(__uint_as_float((unsigned)v[0]), __uint_as_float((unsigned)v[1]),
                                 __uint_as_float((unsigned)v[2]), __uint_as_float((unsigned)v[3]));
            dst[1] = make_float4(__uint_as_float((unsigned)v[4]), __uint_as_float((unsigned)v[5]),
                                 __uint_as_float((unsigned)v[6]), __uint_as_float((unsigned)v[7]));
        }
        __syncthreads();   // S1

        // ---- Single dot: h @ A4, 8 batches, unit = lane ----
        unsigned long long c0 = 0, c1 = 0, c2 = 0, c3 = 0;
        #pragma unroll
        for (int i = 0; i < KCH; i++) {
            const ulonglong2* hv = reinterpret_cast<const ulonglong2*>(&Hs[(kb + i) * HS_STRIDE]);
            ulonglong2 hA = hv[0];
            ulonglong2 hB = hv[1];
            FMA2(c0, hA.x, UU[i]);
            FMA2(c1, hA.y, UU[i]);
            FMA2(c2, hB.x, UU[i]);
            FMA2(c3, hB.y, UU[i]);
        }
        {
            float* rr = &Red[(w * 32 + lane) * RED_STRIDE];
            float x0, x1;
            unpack2(c0, x0, x1); rr[0] = x0; rr[1] = x1;
            unpack2(c1, x0, x1); rr[2] = x0; rr[3] = x1;
            unpack2(c2, x0, x1); rr[4] = x0; rr[5] = x1;
            unpack2(c3, x0, x1); rr[6] = x0; rr[7] = x1;
        }
        __syncthreads();   // S2

        // ---- Reduce + release + output ----
        if (tid < 256) {
            float s = 0.0f;
            #pragma unroll
            for (int ww = 0; ww < NW; ww++)
                s += Red[(ww * 32 + lane) * RED_STRIDE + w];
            float hn = s + psi;
            out[o3] = hn;
            st_tagged(&g_Hx[cur ^ 1][(bg0 + w) * UNITS + u], hn, (unsigned)(r + 2));
        }
        cur ^= 1;
    }
}

// ================================ Launcher ==================================
extern "C" void kernel_launch(void* const* d_in, const int* in_sizes, int n_in,
                              void* d_out, int out_size)
{
    const float* x   = (const float*)d_in[0];   // [64,1024,256]
    const float* Wm  = (const float*)d_in[1];   // [256,512]
    const float* Um  = (const float*)d_in[2];   // [512,512]
    const float* bb  = (const float*)d_in[3];   // [512]
    const float* tau = (const float*)d_in[4];   // [512]
    float* out = (float*)d_out;                 // [64,1024,512]

    (void)in_sizes; (void)n_in; (void)out_size;

    ltc_clear<<<128, 256>>>();

    // A and its powers
    build_A<<<UNITS, UNITS>>>(Um, tau);
    float *pA, *pA2, *pA3, *pA4;
    cudaGetSymbolAddress((void**)&pA,  g_A);
    cudaGetSymbolAddress((void**)&pA2, g_A2);
    cudaGetSymbolAddress((void**)&pA3, g_A3);
    cudaGetSymbolAddress((void**)&pA4, g_A4);
    dim3 sq(UNITS / GBN, UNITS / GBM);
    gemm_sq<<<sq, 256>>>(pA,  pA,  pA2);
    gemm_sq<<<sq, 256>>>(pA2, pA,  pA3);
    gemm_sq<<<sq, 256>>>(pA2, pA2, pA4);

    // G = inv_tau * (x@W + b) -> out
    ltc_gemm<<<dim3(UNITS / GBN, (BATCH * SEQ) / GBM), 256>>>(x, Wm, bb, tau, out);

    // Gamma chain: Gm2 = g0 A + g1; Gm3 = Gm2 A + g2; Psi = Gm3 A + g3
    float *pGm2, *pGm3, *pPsi;
    cudaGetSymbolAddress((void**)&pGm2, g_Gm2);
    cudaGetSymbolAddress((void**)&pGm3, g_Gm3);
    cudaGetSymbolAddress((void**)&pPsi, g_Psi);
    dim3 gg(UNITS / GBN, (BATCH * NR4) / GBM);   // (8, 256)
    gam_chain<<<gg, 256>>>(out,  (size_t)SEQ * UNITS, (size_t)4 * UNITS, out, 1, pGm2);
    gam_chain<<<gg, 256>>>(pGm2, (size_t)NR4 * UNITS, (size_t)UNITS,     out, 2, pGm3);
    gam_chain<<<gg, 256>>>(pGm3, (size_t)NR4 * UNITS, (size_t)UNITS,     out, 3, pPsi);

    // Four-step scan -> out[4r+3]
    ltc_scan<<<dim3(NUC, NBC), SCAN_THREADS>>>(out);

    // Post: out[4r+c] = h_{4r} A^{c+1} + {g, Gm2, Gm3}, c = 0,1,2
    ltc_post<<<dim3(24, (BATCH * NR4) / GBM), 256>>>(out);
}